// round 7
// baseline (speedup 1.0000x reference)
#include <cuda_runtime.h>
#include <cuda_fp16.h>

#define N_NODES 50000
#define N_REL   1000
#define D       128
#define NNZ_MAX 800000

#define SCAN_BLK 512
#define SCAN_NB  ((N_NODES + SCAN_BLK - 1) / SCAN_BLK)   // 98 (< 148 SMs: co-resident)

// Scratch (allocation-free rule: __device__ globals)
__device__ float g_exp_lr[N_REL];
__device__ float g_coef[N_REL];
__device__ float g_S;
__device__ int   g_cnt[N_NODES];
__device__ int   g_bsum[SCAN_NB];
__device__ int   g_done;
__device__ int   g_offs[N_NODES + 1];
__device__ __align__(16) int g_rank[NNZ_MAX];          // rank of edge within its row
__device__ __align__(16) unsigned g_edges[NNZ_MAX];    // packed: col | rel<<16
__device__ __align__(16) __half g_inh[(size_t)N_NODES * D];  // fp16-staged features

// ---------------------------------------------------------------------------
// K1 (prep): fuses three independent jobs across one wide grid:
//   - zero g_cnt / g_S / g_done
//   - relation scores -> exp(leaky_relu)  (warp per relation; shift=0 safe)
//   - convert inlayer f32 -> f16 staging table (grid-stride)
// ---------------------------------------------------------------------------
__global__ void __launch_bounds__(256)
k_prep(const float* __restrict__ inlayer, const float* __restrict__ dual,
       const float* __restrict__ w, const float* __restrict__ b) {
    const int tid    = blockIdx.x * blockDim.x + threadIdx.x;
    const int nthr   = gridDim.x * blockDim.x;
    const int lane   = threadIdx.x & 31;
    const int r      = tid >> 5;

    if (tid == 0) { g_S = 0.f; g_done = 0; }
    for (int i = tid; i < N_NODES; i += nthr) g_cnt[i] = 0;

    // scores (first 1000 warps)
    if (r < N_REL) {
        const float4 a  = reinterpret_cast<const float4*>(dual + (size_t)r * D)[lane];
        const float4 ww = reinterpret_cast<const float4*>(w)[lane];
        float s = a.x * ww.x + a.y * ww.y + a.z * ww.z + a.w * ww.w;
#pragma unroll
        for (int o = 16; o > 0; o >>= 1) s += __shfl_xor_sync(0xffffffffu, s, o);
        if (lane == 0) {
            s += b[0];
            const float lr = (s > 0.f) ? s : 0.01f * s;
            g_exp_lr[r] = expf(lr);
        }
    }

    // fp16 staging: 6.4M floats = 1.6M float4
    const int nv = (N_NODES * D) / 4;
    const float4* in4 = reinterpret_cast<const float4*>(inlayer);
    uint2* out2 = reinterpret_cast<uint2*>(g_inh);
    for (int i = tid; i < nv; i += nthr) {
        const float4 v = __ldg(in4 + i);
        const __half2 h01 = __floats2half2_rn(v.x, v.y);
        const __half2 h23 = __floats2half2_rn(v.z, v.w);
        uint2 p;
        p.x = *reinterpret_cast<const unsigned*>(&h01);
        p.y = *reinterpret_cast<const unsigned*>(&h23);
        out2[i] = p;
    }
}

// ---------------------------------------------------------------------------
// K2: fused row-histogram (capturing per-edge rank) + softmax denominator.
// ---------------------------------------------------------------------------
__global__ void __launch_bounds__(256)
k_hist_sum(const int* __restrict__ rowp, const int* __restrict__ relp, int nnz) {
    const int nvec = nnz >> 2;
    const int4* row4 = reinterpret_cast<const int4*>(rowp);
    const int4* rel4 = reinterpret_cast<const int4*>(relp);
    int4* rank4 = reinterpret_cast<int4*>(g_rank);

    float s = 0.f;
    const int stride = gridDim.x * blockDim.x;
    for (int i = blockIdx.x * blockDim.x + threadIdx.x; i < nvec; i += stride) {
        const int4 r0 = __ldg(row4 + i);
        const int4 q0 = __ldg(rel4 + i);
        int4 rk;
        rk.x = atomicAdd(&g_cnt[r0.x], 1);
        rk.y = atomicAdd(&g_cnt[r0.y], 1);
        rk.z = atomicAdd(&g_cnt[r0.z], 1);
        rk.w = atomicAdd(&g_cnt[r0.w], 1);
        rank4[i] = rk;
        s += g_exp_lr[q0.x] + g_exp_lr[q0.y] + g_exp_lr[q0.z] + g_exp_lr[q0.w];
    }
    const int e0 = (nvec << 2) + blockIdx.x * blockDim.x + threadIdx.x;
    if (e0 < nnz) {
        g_rank[e0] = atomicAdd(&g_cnt[__ldg(rowp + e0)], 1);
        s += g_exp_lr[__ldg(relp + e0)];
    }

#pragma unroll
    for (int o = 16; o > 0; o >>= 1) s += __shfl_xor_sync(0xffffffffu, s, o);
    __shared__ float sm[8];
    if ((threadIdx.x & 31) == 0) sm[threadIdx.x >> 5] = s;
    __syncthreads();
    if (threadIdx.x < 32) {
        float v = (threadIdx.x < (blockDim.x >> 5)) ? sm[threadIdx.x] : 0.f;
#pragma unroll
        for (int o = 4; o > 0; o >>= 1) v += __shfl_xor_sync(0xffffffffu, v, o);
        if (threadIdx.x == 0) atomicAdd(&g_S, v);
    }
}

// ---------------------------------------------------------------------------
// K3: one-kernel scan with software grid barrier (98 co-resident blocks).
// Block 0 also normalizes the coef table.
// ---------------------------------------------------------------------------
__global__ void __launch_bounds__(SCAN_BLK)
k_scan(int nnz) {
    __shared__ int sm[SCAN_BLK];
    const int t   = threadIdx.x;
    const int bid = blockIdx.x;
    const int gid = bid * SCAN_BLK + t;

    if (bid == 0) {
        const float invS = 1.0f / g_S;
        for (int r = t; r < N_REL; r += SCAN_BLK) g_coef[r] = g_exp_lr[r] * invS;
    }

    const int v = (gid < N_NODES) ? g_cnt[gid] : 0;
    sm[t] = v;
    __syncthreads();
#pragma unroll
    for (int o = 1; o < SCAN_BLK; o <<= 1) {
        const int p = (t >= o) ? sm[t - o] : 0;
        __syncthreads();
        sm[t] += p;
        __syncthreads();
    }
    const int incl = sm[t];

    if (t == SCAN_BLK - 1) {
        g_bsum[bid] = incl;
        __threadfence();
        atomicAdd(&g_done, 1);
    }
    if (t == 0) { while (atomicAdd(&g_done, 0) < SCAN_NB) {} }
    __syncthreads();

    sm[t] = (t < bid) ? g_bsum[t] : 0;
    __syncthreads();
#pragma unroll
    for (int o = SCAN_BLK / 2; o > 0; o >>= 1) {
        if (t < o) sm[t] += sm[t + o];
        __syncthreads();
    }
    const int base = sm[0];

    if (gid < N_NODES) g_offs[gid] = base + incl - v;
    if (gid == N_NODES - 1) g_offs[N_NODES] = nnz;
}

// ---------------------------------------------------------------------------
// K4: reorder WITHOUT atomics: pos = offs[row] + rank[e].
// Streaming int4 loads; 4 independent offs-gathers + scatter stores.
// ---------------------------------------------------------------------------
__global__ void __launch_bounds__(256)
k_reorder(const int* __restrict__ rowp, const int* __restrict__ colp,
          const int* __restrict__ relp, int nnz) {
    const int nvec = nnz >> 2;
    const int i = blockIdx.x * blockDim.x + threadIdx.x;
    if (i < nvec) {
        const int4 r  = __ldg(reinterpret_cast<const int4*>(rowp) + i);
        const int4 c  = __ldg(reinterpret_cast<const int4*>(colp) + i);
        const int4 q  = __ldg(reinterpret_cast<const int4*>(relp) + i);
        const int4 rk = __ldg(reinterpret_cast<const int4*>(g_rank) + i);
        const int p0 = __ldg(&g_offs[r.x]) + rk.x;
        const int p1 = __ldg(&g_offs[r.y]) + rk.y;
        const int p2 = __ldg(&g_offs[r.z]) + rk.z;
        const int p3 = __ldg(&g_offs[r.w]) + rk.w;
        g_edges[p0] = (unsigned)c.x | ((unsigned)q.x << 16);
        g_edges[p1] = (unsigned)c.y | ((unsigned)q.y << 16);
        g_edges[p2] = (unsigned)c.z | ((unsigned)q.z << 16);
        g_edges[p3] = (unsigned)c.w | ((unsigned)q.w << 16);
    }
    const int e = (nvec << 2) + i;
    if (e < nnz) {
        const int pos = __ldg(&g_offs[__ldg(rowp + e)]) + g_rank[e];
        g_edges[pos] = (unsigned)__ldg(colp + e) | ((unsigned)__ldg(relp + e) << 16);
    }
}

// ---------------------------------------------------------------------------
// K5: gather SpMM over fp16-staged features. Warp per row; uint4 broadcast
// edge loads (4 edges/load); per edge each lane loads 8B (4 halfs) -> 256B/warp.
// fp32 accumulation, fp32 coalesced store.
// ---------------------------------------------------------------------------
__device__ __forceinline__ void acc_edge_h(unsigned p, int lane, float4& a) {
    const int   col = (int)(p & 0xFFFFu);
    const float c   = g_coef[p >> 16];
    const uint2 hv  = __ldg(reinterpret_cast<const uint2*>(
                                g_inh + (size_t)col * D) + lane);
    const __half2 h01 = *reinterpret_cast<const __half2*>(&hv.x);
    const __half2 h23 = *reinterpret_cast<const __half2*>(&hv.y);
    const float2 f01 = __half22float2(h01);
    const float2 f23 = __half22float2(h23);
    a.x += c * f01.x; a.y += c * f01.y; a.z += c * f23.x; a.w += c * f23.y;
}

__global__ void __launch_bounds__(256)
k_gather(float* __restrict__ out) {
    const int lane = threadIdx.x & 31;
    const int row  = (blockIdx.x * blockDim.x + threadIdx.x) >> 5;
    if (row >= N_NODES) return;

    const int s = __ldg(&g_offs[row]);
    const int e = __ldg(&g_offs[row + 1]);

    float4 a0 = make_float4(0.f, 0.f, 0.f, 0.f);
    float4 a1 = make_float4(0.f, 0.f, 0.f, 0.f);
    float4 a2 = make_float4(0.f, 0.f, 0.f, 0.f);
    float4 a3 = make_float4(0.f, 0.f, 0.f, 0.f);

    int i = s;
    while (i < e && (i & 3)) { acc_edge_h(__ldg(&g_edges[i]), lane, a0); i++; }
    for (; i + 3 < e; i += 4) {
        const uint4 p = __ldg(reinterpret_cast<const uint4*>(g_edges + i));
        acc_edge_h(p.x, lane, a0);
        acc_edge_h(p.y, lane, a1);
        acc_edge_h(p.z, lane, a2);
        acc_edge_h(p.w, lane, a3);
    }
    for (; i < e; i++) acc_edge_h(__ldg(&g_edges[i]), lane, a0);

    a0.x += a1.x + a2.x + a3.x;
    a0.y += a1.y + a2.y + a3.y;
    a0.z += a1.z + a2.z + a3.z;
    a0.w += a1.w + a2.w + a3.w;
    reinterpret_cast<float4*>(out + (size_t)row * D)[lane] = a0;
}

// ---------------------------------------------------------------------------
// kernel_launch
// Inputs: 0 inlayer [N,D] f32 | 1 dual [R,D] f32 | 2 conv_w [D] f32
//         3 conv_b [1] f32    | 4 edge_idx [2,NNZ] i32 | 5 edge_rel [NNZ] i32
// Output: [N, D] f32
// ---------------------------------------------------------------------------
extern "C" void kernel_launch(void* const* d_in, const int* in_sizes, int n_in,
                              void* d_out, int out_size) {
    const float* inlayer = (const float*)d_in[0];
    const float* dual    = (const float*)d_in[1];
    const float* conv_w  = (const float*)d_in[2];
    const float* conv_b  = (const float*)d_in[3];
    const int*   eidx    = (const int*)d_in[4];
    const int*   erel    = (const int*)d_in[5];
    float*       out     = (float*)d_out;

    const int nnz = in_sizes[5];
    const int* rowp = eidx;
    const int* colp = eidx + nnz;

    k_prep<<<592, 256>>>(inlayer, dual, conv_w, conv_b);
    k_hist_sum<<<592, 256>>>(rowp, erel, nnz);
    k_scan<<<SCAN_NB, SCAN_BLK>>>(nnz);
    k_reorder<<<(nnz / 4 + 255) / 256, 256>>>(rowp, colp, erel, nnz);
    k_gather<<<(N_NODES * 32 + 255) / 256, 256>>>(out);
}

// round 8
// speedup vs baseline: 1.0556x; 1.0556x over previous
#include <cuda_runtime.h>

#define N_NODES 50000
#define N_REL   1000
#define D       128
#define NNZ_MAX 800000

#define FUSE_NB  592          // exactly 4 blocks/SM on 148 SMs -> co-resident
#define SCAN_BLK 512
#define SCAN_NB  ((N_NODES + SCAN_BLK - 1) / SCAN_BLK)   // 98

// Scratch (allocation-free rule: __device__ globals)
__device__ float g_exp_lr[N_REL];
__device__ float g_coef[N_REL];
__device__ float g_S;
__device__ int   g_cnt[N_NODES];
__device__ int   g_bsum[SCAN_NB];
__device__ int   g_bar1;              // K1 grid barrier (reset by K2)
__device__ int   g_bar2;              // K2 grid barrier (reset by K3)
__device__ int   g_offs[N_NODES + 1];
__device__ __align__(16) int g_rank[NNZ_MAX];        // edge's rank within its row
__device__ __align__(16) unsigned g_edges[NNZ_MAX];  // packed: col | rel<<16

// ---------------------------------------------------------------------------
// K1 (fused prep + hist):
//  phase A: zero g_cnt/g_S, compute relation scores (warp/relation, shift=0
//           safe by softmax shift-invariance with O(1) inputs)
//  -- software grid barrier (592 co-resident blocks) --
//  phase B: row-histogram capturing per-edge rank + softmax denominator.
// ---------------------------------------------------------------------------
__global__ void __launch_bounds__(256, 4)
k_fused(const float* __restrict__ dual, const float* __restrict__ w,
        const float* __restrict__ b,
        const int* __restrict__ rowp, const int* __restrict__ relp, int nnz) {
    const int tid  = blockIdx.x * blockDim.x + threadIdx.x;
    const int nthr = gridDim.x * blockDim.x;
    const int lane = threadIdx.x & 31;
    const int r    = tid >> 5;

    // ---- phase A ----
    if (tid == 0) { g_S = 0.f; g_bar2 = 0; }
    for (int i = tid; i < N_NODES; i += nthr) g_cnt[i] = 0;

    if (r < N_REL) {
        const float4 a  = reinterpret_cast<const float4*>(dual + (size_t)r * D)[lane];
        const float4 ww = reinterpret_cast<const float4*>(w)[lane];
        float s = a.x * ww.x + a.y * ww.y + a.z * ww.z + a.w * ww.w;
#pragma unroll
        for (int o = 16; o > 0; o >>= 1) s += __shfl_xor_sync(0xffffffffu, s, o);
        if (lane == 0) {
            s += b[0];
            const float lr = (s > 0.f) ? s : 0.01f * s;
            g_exp_lr[r] = expf(lr);
        }
    }

    // ---- grid barrier ----
    __syncthreads();
    __threadfence();
    if (threadIdx.x == 0) {
        atomicAdd(&g_bar1, 1);
        while (atomicAdd(&g_bar1, 0) < FUSE_NB) {}
    }
    __syncthreads();

    // ---- phase B: histogram + rank + denominator ----
    const int nvec = nnz >> 2;
    const int4* row4 = reinterpret_cast<const int4*>(rowp);
    const int4* rel4 = reinterpret_cast<const int4*>(relp);
    int4* rank4 = reinterpret_cast<int4*>(g_rank);

    float s = 0.f;
    for (int i = tid; i < nvec; i += nthr) {
        const int4 r0 = __ldg(row4 + i);
        const int4 q0 = __ldg(rel4 + i);
        int4 rk;
        rk.x = atomicAdd(&g_cnt[r0.x], 1);
        rk.y = atomicAdd(&g_cnt[r0.y], 1);
        rk.z = atomicAdd(&g_cnt[r0.z], 1);
        rk.w = atomicAdd(&g_cnt[r0.w], 1);
        rank4[i] = rk;
        s += g_exp_lr[q0.x] + g_exp_lr[q0.y] + g_exp_lr[q0.z] + g_exp_lr[q0.w];
    }
    const int e0 = (nvec << 2) + tid;
    if (e0 < nnz) {
        g_rank[e0] = atomicAdd(&g_cnt[__ldg(rowp + e0)], 1);
        s += g_exp_lr[__ldg(relp + e0)];
    }

#pragma unroll
    for (int o = 16; o > 0; o >>= 1) s += __shfl_xor_sync(0xffffffffu, s, o);
    __shared__ float sm[8];
    if ((threadIdx.x & 31) == 0) sm[threadIdx.x >> 5] = s;
    __syncthreads();
    if (threadIdx.x < 32) {
        float v = (threadIdx.x < (blockDim.x >> 5)) ? sm[threadIdx.x] : 0.f;
#pragma unroll
        for (int o = 4; o > 0; o >>= 1) v += __shfl_xor_sync(0xffffffffu, v, o);
        if (threadIdx.x == 0) atomicAdd(&g_S, v);
    }
}

// ---------------------------------------------------------------------------
// K2: scan with software grid barrier (98 co-resident blocks). Block 0 also
// normalizes the coef table. Resets g_bar1 for the next graph replay.
// ---------------------------------------------------------------------------
__global__ void __launch_bounds__(SCAN_BLK)
k_scan(int nnz) {
    __shared__ int sm[SCAN_BLK];
    const int t   = threadIdx.x;
    const int bid = blockIdx.x;
    const int gid = bid * SCAN_BLK + t;

    if (bid == 0 && t == 0) g_bar1 = 0;          // reset K1's barrier
    if (bid == 0) {
        const float invS = 1.0f / g_S;
        for (int r = t; r < N_REL; r += SCAN_BLK) g_coef[r] = g_exp_lr[r] * invS;
    }

    const int v = (gid < N_NODES) ? g_cnt[gid] : 0;
    sm[t] = v;
    __syncthreads();
#pragma unroll
    for (int o = 1; o < SCAN_BLK; o <<= 1) {
        const int p = (t >= o) ? sm[t - o] : 0;
        __syncthreads();
        sm[t] += p;
        __syncthreads();
    }
    const int incl = sm[t];

    if (t == SCAN_BLK - 1) {
        g_bsum[bid] = incl;
        __threadfence();
        atomicAdd(&g_bar2, 1);
    }
    if (t == 0) { while (atomicAdd(&g_bar2, 0) < SCAN_NB) {} }
    __syncthreads();

    sm[t] = (t < bid) ? g_bsum[t] : 0;
    __syncthreads();
#pragma unroll
    for (int o = SCAN_BLK / 2; o > 0; o >>= 1) {
        if (t < o) sm[t] += sm[t + o];
        __syncthreads();
    }
    const int base = sm[0];

    if (gid < N_NODES) g_offs[gid] = base + incl - v;
    if (gid == N_NODES - 1) g_offs[N_NODES] = nnz;
}

// ---------------------------------------------------------------------------
// K3: reorder WITHOUT atomics (pos = offs[row] + rank), 8 edges per thread
// (2x int4 groups) for deep latency overlap.
// ---------------------------------------------------------------------------
__global__ void __launch_bounds__(256)
k_reorder(const int* __restrict__ rowp, const int* __restrict__ colp,
          const int* __restrict__ relp, int nnz) {
    if (blockIdx.x == 0 && threadIdx.x == 0) g_bar2 = 0;   // reset K2's barrier

    const int nvec = nnz >> 2;
    const int tid  = blockIdx.x * blockDim.x + threadIdx.x;
    const int i0   = tid * 2;
    const int i1   = i0 + 1;

#pragma unroll
    for (int k = 0; k < 2; k++) {
        const int i = (k == 0) ? i0 : i1;
        if (i < nvec) {
            const int4 r  = __ldg(reinterpret_cast<const int4*>(rowp) + i);
            const int4 c  = __ldg(reinterpret_cast<const int4*>(colp) + i);
            const int4 q  = __ldg(reinterpret_cast<const int4*>(relp) + i);
            const int4 rk = __ldg(reinterpret_cast<const int4*>(g_rank) + i);
            const int p0 = __ldg(&g_offs[r.x]) + rk.x;
            const int p1 = __ldg(&g_offs[r.y]) + rk.y;
            const int p2 = __ldg(&g_offs[r.z]) + rk.z;
            const int p3 = __ldg(&g_offs[r.w]) + rk.w;
            g_edges[p0] = (unsigned)c.x | ((unsigned)q.x << 16);
            g_edges[p1] = (unsigned)c.y | ((unsigned)q.y << 16);
            g_edges[p2] = (unsigned)c.z | ((unsigned)q.z << 16);
            g_edges[p3] = (unsigned)c.w | ((unsigned)q.w << 16);
        }
    }
    // tail (nnz % 4)
    const int e = (nvec << 2) + tid;
    if (e < nnz) {
        const int pos = __ldg(&g_offs[__ldg(rowp + e)]) + g_rank[e];
        g_edges[pos] = (unsigned)__ldg(colp + e) | ((unsigned)__ldg(relp + e) << 16);
    }
}

// ---------------------------------------------------------------------------
// K4: gather SpMM (fp32 features). Warp per row; uint4 broadcast edge loads
// (4 edges/load); 4 independent 512B gathers in flight; coalesced store.
// ---------------------------------------------------------------------------
__device__ __forceinline__ void acc_edge(unsigned p, int lane,
                                         const float* __restrict__ inlayer,
                                         float4& a) {
    const int   col = (int)(p & 0xFFFFu);
    const float c   = g_coef[p >> 16];
    const float4 v  = __ldg(reinterpret_cast<const float4*>(
                                inlayer + (size_t)col * D) + lane);
    a.x += c * v.x; a.y += c * v.y; a.z += c * v.z; a.w += c * v.w;
}

__global__ void __launch_bounds__(256)
k_gather(const float* __restrict__ inlayer, float* __restrict__ out) {
    const int lane = threadIdx.x & 31;
    const int row  = (blockIdx.x * blockDim.x + threadIdx.x) >> 5;
    if (row >= N_NODES) return;

    const int s = __ldg(&g_offs[row]);
    const int e = __ldg(&g_offs[row + 1]);

    float4 a0 = make_float4(0.f, 0.f, 0.f, 0.f);
    float4 a1 = make_float4(0.f, 0.f, 0.f, 0.f);
    float4 a2 = make_float4(0.f, 0.f, 0.f, 0.f);
    float4 a3 = make_float4(0.f, 0.f, 0.f, 0.f);

    int i = s;
    while (i < e && (i & 3)) { acc_edge(__ldg(&g_edges[i]), lane, inlayer, a0); i++; }
    for (; i + 3 < e; i += 4) {
        const uint4 p = __ldg(reinterpret_cast<const uint4*>(g_edges + i));
        acc_edge(p.x, lane, inlayer, a0);
        acc_edge(p.y, lane, inlayer, a1);
        acc_edge(p.z, lane, inlayer, a2);
        acc_edge(p.w, lane, inlayer, a3);
    }
    for (; i < e; i++) acc_edge(__ldg(&g_edges[i]), lane, inlayer, a0);

    a0.x += a1.x + a2.x + a3.x;
    a0.y += a1.y + a2.y + a3.y;
    a0.z += a1.z + a2.z + a3.z;
    a0.w += a1.w + a2.w + a3.w;
    reinterpret_cast<float4*>(out + (size_t)row * D)[lane] = a0;
}

// ---------------------------------------------------------------------------
// kernel_launch
// Inputs: 0 inlayer [N,D] f32 | 1 dual [R,D] f32 | 2 conv_w [D] f32
//         3 conv_b [1] f32    | 4 edge_idx [2,NNZ] i32 | 5 edge_rel [NNZ] i32
// Output: [N, D] f32
// ---------------------------------------------------------------------------
extern "C" void kernel_launch(void* const* d_in, const int* in_sizes, int n_in,
                              void* d_out, int out_size) {
    const float* inlayer = (const float*)d_in[0];
    const float* dual    = (const float*)d_in[1];
    const float* conv_w  = (const float*)d_in[2];
    const float* conv_b  = (const float*)d_in[3];
    const int*   eidx    = (const int*)d_in[4];
    const int*   erel    = (const int*)d_in[5];
    float*       out     = (float*)d_out;

    const int nnz = in_sizes[5];
    const int* rowp = eidx;
    const int* colp = eidx + nnz;

    k_fused<<<FUSE_NB, 256>>>(dual, conv_w, conv_b, rowp, erel, nnz);
    k_scan<<<SCAN_NB, SCAN_BLK>>>(nnz);
    k_reorder<<<(nnz / 8 + 255) / 256, 256>>>(rowp, colp, erel, nnz);
    k_gather<<<(N_NODES * 32 + 255) / 256, 256>>>(inlayer, out);
}